// round 1
// baseline (speedup 1.0000x reference)
#include <cuda_runtime.h>
#include <math.h>

// Shapes (fixed by the problem)
#define BB   4
#define NN   2048
#define DD   1024
#define DLL  64
#define DKK  128
#define DCC  8

// -------- device scratch (static: no allocations allowed) --------
__device__ float g_basis[DCC*DKK*DKK];   // skew-combined basis [r][i][j]
__device__ float g_q[BB*DKK];            // q / tau
__device__ float g_qB[BB*DCC*DKK];       // (q/tau)^T basis_r
__device__ float g_lam[BB];
__device__ float g_kv[(size_t)BB*NN*256];// [b][n][0:128]=k, [128:256]=v  (8 MB)
__device__ float g_score[BB*NN];
__device__ float g_screen[BB*NN];
__device__ float g_m[BB];
__device__ float g_Z[BB];
__device__ float g_avp[BB*16*DKK];
__device__ float g_av[BB*DKK];

// -------- K1: basis = G_S*skew(b) + G_2*skew(e) + G_1*skew(o) --------
__global__ void k_basis(const float* __restrict__ bb, const float* __restrict__ be,
                        const float* __restrict__ bo) {
    int idx = blockIdx.x * blockDim.x + threadIdx.x;
    if (idx >= DCC*DKK*DKK) return;
    int r = idx >> 14, rem = idx & 16383, i = rem >> 7, j = rem & 127;
    int tidx = (r << 14) | (j << 7) | i;   // transposed element
    g_basis[idx] = 1.0f*(bb[idx]-bb[tidx]) + 0.5f*(be[idx]-be[tidx]) + 0.3f*(bo[idx]-bo[tidx]);
}

// -------- K2: q[b,a] = xq.WQ + zq.WQz + zq^T G_a zq, scaled by 1/tau --------
__global__ void k_query(const float* __restrict__ xq, const float* __restrict__ zq,
                        const float* __restrict__ WQ, const float* __restrict__ WQz,
                        const float* __restrict__ WQg) {
    int a = blockIdx.x, b = blockIdx.y;
    int t = threadIdx.x;                   // 128 threads
    __shared__ float zs[DLL];
    __shared__ float red[128];
    if (t < DLL) zs[t] = zq[b*DLL + t];
    __syncthreads();
    float s = 0.f;
    const float* wq = WQ + a*DD;
    const float* x  = xq + b*DD;
    for (int d = t; d < DD; d += 128) s += x[d]*wq[d];
    if (t < DLL) s += zs[t]*WQz[a*DLL + t];
    const float* G = WQg + a*DLL*DLL;
    for (int idx = t; idx < DLL*DLL; idx += 128) {
        int i = idx >> 6, j = idx & 63;
        s += G[idx]*zs[i]*zs[j];
    }
    red[t] = s; __syncthreads();
    for (int off = 64; off > 0; off >>= 1) {
        if (t < off) red[t] += red[t+off];
        __syncthreads();
    }
    if (t == 0) {
        float rsq = 0.f;
        for (int l = 0; l < DLL; l++) rsq += zs[l]*zs[l];
        rsq = fminf(rsq, 1.f - 1e-6f);
        float lam = 2.f/(1.f - rsq + 1e-6f);
        float tau = sqrtf((float)DKK)/lam;
        g_q[b*DKK + a] = red[0]/tau;
        if (a == 0) g_lam[b] = lam;
    }
}

// -------- K3: qB[b,r,j] = sum_i q[b,i]*basis[r,i,j] --------
__global__ void k_qB() {
    int r = blockIdx.x, b = blockIdx.y;
    int j = threadIdx.x;                   // 128 threads
    const float* Br = g_basis + r*DKK*DKK;
    const float* qb = g_q + b*DKK;
    float acc = 0.f;
    #pragma unroll 8
    for (int i = 0; i < DKK; i++) acc += qb[i]*Br[i*DKK + j];
    g_qB[(b*DCC + r)*DKK + j] = acc;
}

// -------- K4: fused K/V GEMM: C[m, 0:256] = x_keys[m,:] . [W_K;W_V]^T --------
// M=8192, N=256 (4 col-blocks of 64), K=1024. BM=128 BN=64 BK=16 TM=8 TN=4, 256 thr.
__global__ __launch_bounds__(256) void k_gemm(const float* __restrict__ A,
                                              const float* __restrict__ WK,
                                              const float* __restrict__ WV) {
    __shared__ float As[16][128];
    __shared__ float Bs[16][64];
    const int tid = threadIdx.x;
    const int ty = tid >> 4, tx = tid & 15;
    const int mBase = blockIdx.x * 128;
    const int nb = blockIdx.y;
    const float* Bp = (nb < 2) ? (WK + (size_t)nb*64*DD) : (WV + (size_t)(nb-2)*64*DD);
    const float* Ap = A + (size_t)mBase * DD;

    float acc[8][4];
    #pragma unroll
    for (int i = 0; i < 8; i++)
        #pragma unroll
        for (int j = 0; j < 4; j++) acc[i][j] = 0.f;

    const int ar0 = tid >> 2;              // 0..63
    const int ar1 = ar0 + 64;
    const int ac  = (tid & 3) * 4;
    const int br  = tid >> 2;              // 0..63
    const int bc  = (tid & 3) * 4;

    for (int k0 = 0; k0 < DD; k0 += 16) {
        float4 va0 = *(const float4*)(Ap + (size_t)ar0*DD + k0 + ac);
        float4 va1 = *(const float4*)(Ap + (size_t)ar1*DD + k0 + ac);
        float4 vb  = *(const float4*)(Bp + (size_t)br*DD + k0 + bc);
        As[ac+0][ar0]=va0.x; As[ac+1][ar0]=va0.y; As[ac+2][ar0]=va0.z; As[ac+3][ar0]=va0.w;
        As[ac+0][ar1]=va1.x; As[ac+1][ar1]=va1.y; As[ac+2][ar1]=va1.z; As[ac+3][ar1]=va1.w;
        Bs[bc+0][br]=vb.x;   Bs[bc+1][br]=vb.y;   Bs[bc+2][br]=vb.z;   Bs[bc+3][br]=vb.w;
        __syncthreads();
        #pragma unroll
        for (int k = 0; k < 16; k++) {
            float4 a0 = *(const float4*)&As[k][ty*8];
            float4 a1 = *(const float4*)&As[k][ty*8+4];
            float4 b4 = *(const float4*)&Bs[k][tx*4];
            float av[8] = {a0.x,a0.y,a0.z,a0.w,a1.x,a1.y,a1.z,a1.w};
            float bv[4] = {b4.x,b4.y,b4.z,b4.w};
            #pragma unroll
            for (int i = 0; i < 8; i++)
                #pragma unroll
                for (int j = 0; j < 4; j++) acc[i][j] += av[i]*bv[j];
        }
        __syncthreads();
    }
    #pragma unroll
    for (int i = 0; i < 8; i++) {
        float4 o = make_float4(acc[i][0], acc[i][1], acc[i][2], acc[i][3]);
        *(float4*)(g_kv + (size_t)(mBase + ty*8 + i)*256 + nb*64 + tx*4) = o;
    }
}

// -------- K5: per-(b,n) score + screening factor (one warp each) --------
__global__ void k_score(const float* __restrict__ zq, const float* __restrict__ zk,
                        const float* __restrict__ Wd, const float* __restrict__ logsig) {
    int gw = (blockIdx.x * blockDim.x + threadIdx.x) >> 5;
    if (gw >= BB*NN) return;
    int lane = threadIdx.x & 31;
    int b = gw >> 11, n = gw & (NN-1);

    float zq0 = zq[b*DLL + lane], zq1 = zq[b*DLL + 32 + lane];
    const float* zkp = zk + (size_t)(b*NN + n)*DLL;
    float d0 = zq0 - zkp[lane];
    float d1 = zq1 - zkp[32 + lane];

    float dist = d0*d0 + d1*d1;
    #pragma unroll
    for (int o = 16; o; o >>= 1) dist += __shfl_xor_sync(0xffffffffu, dist, o);

    float coeff[DCC];
    #pragma unroll
    for (int r = 0; r < DCC; r++) {
        float p = d0*Wd[r*DLL + lane] + d1*Wd[r*DLL + 32 + lane];
        #pragma unroll
        for (int o = 16; o; o >>= 1) p += __shfl_xor_sync(0xffffffffu, p, o);
        coeff[r] = p;
    }

    float s = 0.f;
    const float* kvp = g_kv + (size_t)(b*NN + n)*256;
    #pragma unroll
    for (int jj = 0; jj < 4; jj++) {
        int j = jj*32 + lane;
        float qe = g_q[b*DKK + j];
        #pragma unroll
        for (int r = 0; r < DCC; r++) qe += coeff[r]*g_qB[(b*DCC + r)*DKK + j];
        s += qe * kvp[j];
    }
    #pragma unroll
    for (int o = 16; o; o >>= 1) s += __shfl_xor_sync(0xffffffffu, s, o);

    if (lane == 0) {
        g_score[b*NN + n] = s;
        float lam = g_lam[b];
        float sig = expf(logsig[0]);
        g_screen[b*NN + n] = expf(-sig * 0.5f * lam * lam * dist);
    }
}

// -------- K6: per-b softmax stats (max, sum-exp) --------
__global__ void k_smax() {
    int b = blockIdx.x, t = threadIdx.x;   // 256 threads
    __shared__ float red[256];
    float m = -1e30f;
    for (int i = t; i < NN; i += 256) m = fmaxf(m, g_score[b*NN + i]);
    red[t] = m; __syncthreads();
    for (int o = 128; o; o >>= 1) { if (t < o) red[t] = fmaxf(red[t], red[t+o]); __syncthreads(); }
    m = red[0]; __syncthreads();
    float z = 0.f;
    for (int i = t; i < NN; i += 256) z += expf(g_score[b*NN + i] - m);
    red[t] = z; __syncthreads();
    for (int o = 128; o; o >>= 1) { if (t < o) red[t] += red[t+o]; __syncthreads(); }
    if (t == 0) { g_m[b] = m; g_Z[b] = red[0]; }
}

// -------- K7: partial av[b,a] = sum_n w_n * v[b,n,a] over 128-n slices --------
__global__ void k_av() {
    int b = blockIdx.x, s0 = blockIdx.y * 128;
    int t = threadIdx.x;                   // 128 threads (a index)
    __shared__ float w[128];
    int n = s0 + t;
    w[t] = expf(g_score[b*NN + n] - g_m[b]) / g_Z[b] * g_screen[b*NN + n];
    __syncthreads();
    float acc = 0.f;
    const float* vbase = g_kv + (size_t)(b*NN + s0)*256 + 128 + t;
    #pragma unroll 4
    for (int nn = 0; nn < 128; nn++) acc += w[nn] * vbase[(size_t)nn*256];
    g_avp[(b*16 + blockIdx.y)*DKK + t] = acc;
}

// -------- K7b: reduce partials --------
__global__ void k_avred() {
    int idx = threadIdx.x;                 // 512 threads
    int b = idx >> 7, a = idx & 127;
    float s = 0.f;
    #pragma unroll
    for (int p = 0; p < 16; p++) s += g_avp[(b*16 + p)*DKK + a];
    g_av[idx] = s;
}

// -------- K8: out[b,d] = sum_a av[b,a]*W_O[d,a] --------
__global__ void k_out(const float* __restrict__ WO, float* __restrict__ out) {
    int t = threadIdx.x;                   // 256 threads
    int idx = blockIdx.x * 256 + t;
    int b = idx >> 10, d = idx & 1023;
    __shared__ float av[DKK];
    if (t < DKK) av[t] = g_av[b*DKK + t];
    __syncthreads();
    float s = 0.f;
    const float4* wo = (const float4*)(WO + (size_t)d*DKK);
    #pragma unroll 8
    for (int a4 = 0; a4 < 32; a4++) {
        float4 wv = wo[a4];
        s += av[a4*4+0]*wv.x + av[a4*4+1]*wv.y + av[a4*4+2]*wv.z + av[a4*4+3]*wv.w;
    }
    out[idx] = s;
}

extern "C" void kernel_launch(void* const* d_in, const int* in_sizes, int n_in,
                              void* d_out, int out_size) {
    const float* x_query   = (const float*)d_in[0];
    const float* z_query   = (const float*)d_in[1];
    const float* x_keys    = (const float*)d_in[2];
    const float* z_keys    = (const float*)d_in[3];
    const float* W_Q       = (const float*)d_in[4];
    const float* W_Qz      = (const float*)d_in[5];
    const float* W_Qg      = (const float*)d_in[6];
    const float* W_K       = (const float*)d_in[7];
    const float* W_V       = (const float*)d_in[8];
    const float* W_O       = (const float*)d_in[9];
    const float* W_delta   = (const float*)d_in[10];
    const float* basis_b   = (const float*)d_in[11];
    const float* basis_e   = (const float*)d_in[12];
    const float* basis_o   = (const float*)d_in[13];
    const float* log_sigma = (const float*)d_in[14];
    float* out = (float*)d_out;

    k_basis<<<(DCC*DKK*DKK + 255)/256, 256>>>(basis_b, basis_e, basis_o);
    k_query<<<dim3(DKK, BB), 128>>>(x_query, z_query, W_Q, W_Qz, W_Qg);
    k_qB<<<dim3(DCC, BB), 128>>>();
    k_gemm<<<dim3(64, 4), 256>>>(x_keys, W_K, W_V);
    k_score<<<(BB*NN*32)/256, 256>>>(z_query, z_keys, W_delta, log_sigma);
    k_smax<<<BB, 256>>>();
    k_av<<<dim3(BB, 16), 128>>>();
    k_avred<<<1, 512>>>();
    k_out<<<16, 256>>>(W_O, out);
}

// round 3
// speedup vs baseline: 1.9389x; 1.9389x over previous
#include <cuda_runtime.h>
#include <cuda_bf16.h>
#include <math.h>
#include <stdint.h>

// Shapes (fixed by the problem)
#define BB   4
#define NN   2048
#define DD   1024
#define DLL  64
#define DKK  128
#define DCC  8

// -------- device scratch (static: no allocations allowed) --------
__device__ float g_basis[DCC*DKK*DKK];   // skew-combined basis [r][i][j]
__device__ float g_q[BB*DKK];            // q / tau
__device__ float g_qB[BB*DCC*DKK];       // (q/tau)^T basis_r
__device__ float g_lam[BB];
__device__ float g_kv[(size_t)BB*NN*256];// [b][n][0:128]=k, [128:256]=v  (8 MB)
__device__ float g_score[BB*NN];
__device__ float g_screen[BB*NN];
__device__ float g_m[BB];
__device__ float g_Z[BB];
__device__ float g_avp[BB*16*DKK];
__device__ float g_av[BB*DKK];

// ================= helpers =================
__device__ __forceinline__ uint32_t smem_u32(const void* p) {
    uint32_t a;
    asm("{ .reg .u64 t; cvta.to.shared.u64 t, %1; cvt.u32.u64 %0, t; }" : "=r"(a) : "l"(p));
    return a;
}

#define SWZ128(off) ((off) ^ (((off) >> 3) & 0x70))

#define LDSM_X4(r, addr) \
    asm volatile("ldmatrix.sync.aligned.m8n8.x4.shared.b16 {%0,%1,%2,%3}, [%4];" \
        : "=r"((r)[0]), "=r"((r)[1]), "=r"((r)[2]), "=r"((r)[3]) : "r"(addr))
#define LDSM_X2(r, addr) \
    asm volatile("ldmatrix.sync.aligned.m8n8.x2.shared.b16 {%0,%1}, [%2];" \
        : "=r"((r)[0]), "=r"((r)[1]) : "r"(addr))

__device__ __forceinline__ void mma16816(float* c, const uint32_t* a, const uint32_t* b) {
    asm volatile(
        "mma.sync.aligned.m16n8k16.row.col.f32.bf16.bf16.f32 "
        "{%0,%1,%2,%3}, {%4,%5,%6,%7}, {%8,%9}, {%0,%1,%2,%3};"
        : "+f"(c[0]), "+f"(c[1]), "+f"(c[2]), "+f"(c[3])
        : "r"(a[0]), "r"(a[1]), "r"(a[2]), "r"(a[3]), "r"(b[0]), "r"(b[1]));
}

// -------- K1: basis = G_S*skew(b) + G_2*skew(e) + G_1*skew(o) --------
__global__ void k_basis(const float* __restrict__ bb, const float* __restrict__ be,
                        const float* __restrict__ bo) {
    int idx = blockIdx.x * blockDim.x + threadIdx.x;
    if (idx >= DCC*DKK*DKK) return;
    int r = idx >> 14, rem = idx & 16383, i = rem >> 7, j = rem & 127;
    int tidx = (r << 14) | (j << 7) | i;   // transposed element
    g_basis[idx] = 1.0f*(bb[idx]-bb[tidx]) + 0.5f*(be[idx]-be[tidx]) + 0.3f*(bo[idx]-bo[tidx]);
}

// -------- K2: q[b,a] = xq.WQ + zq.WQz + zq^T G_a zq, scaled by 1/tau --------
__global__ void k_query(const float* __restrict__ xq, const float* __restrict__ zq,
                        const float* __restrict__ WQ, const float* __restrict__ WQz,
                        const float* __restrict__ WQg) {
    int a = blockIdx.x, b = blockIdx.y;
    int t = threadIdx.x;                   // 128 threads
    __shared__ float zs[DLL];
    __shared__ float red[128];
    if (t < DLL) zs[t] = zq[b*DLL + t];
    __syncthreads();
    float s = 0.f;
    const float* wq = WQ + a*DD;
    const float* x  = xq + b*DD;
    for (int d = t; d < DD; d += 128) s += x[d]*wq[d];
    if (t < DLL) s += zs[t]*WQz[a*DLL + t];
    const float* G = WQg + a*DLL*DLL;
    for (int idx = t; idx < DLL*DLL; idx += 128) {
        int i = idx >> 6, j = idx & 63;
        s += G[idx]*zs[i]*zs[j];
    }
    red[t] = s; __syncthreads();
    for (int off = 64; off > 0; off >>= 1) {
        if (t < off) red[t] += red[t+off];
        __syncthreads();
    }
    if (t == 0) {
        float rsq = 0.f;
        for (int l = 0; l < DLL; l++) rsq += zs[l]*zs[l];
        rsq = fminf(rsq, 1.f - 1e-6f);
        float lam = 2.f/(1.f - rsq + 1e-6f);
        float tau = sqrtf((float)DKK)/lam;
        g_q[b*DKK + a] = red[0]/tau;
        if (a == 0) g_lam[b] = lam;
    }
}

// -------- K3: qB[b,r,j] = sum_i q[b,i]*basis[r,i,j] --------
__global__ void k_qB() {
    int r = blockIdx.x, b = blockIdx.y;
    int j = threadIdx.x;                   // 128 threads
    const float* Br = g_basis + r*DKK*DKK;
    const float* qb = g_q + b*DKK;
    float acc = 0.f;
    #pragma unroll 8
    for (int i = 0; i < DKK; i++) acc += qb[i]*Br[i*DKK + j];
    g_qB[(b*DCC + r)*DKK + j] = acc;
}

// ============ K4: mma.sync bf16 3-split K/V GEMM ============
// C[8192, 256] = x_keys[8192,1024] . [W_K; W_V]^T via Ahi.Bhi + Alo.Bhi + Ahi.Blo.
// CTA tile 128(M) x 128(N), warp tile 32x64, K-chunks of 64, 2-stage pipeline.
#define GT       256
#define NCHUNK   16          // 1024 / 64
#define OFF_AHI  0
#define OFF_ALO  16384
#define OFF_BHI  32768
#define OFF_BLO  49152
#define STAGE_SZ 65536
#define GEMM_SMEM (2*STAGE_SZ)

__device__ __forceinline__ void cvt_f4(float4 v, char* hiP, char* loP) {
    __nv_bfloat16 h0 = __float2bfloat16(v.x);
    __nv_bfloat16 h1 = __float2bfloat16(v.y);
    __nv_bfloat16 h2 = __float2bfloat16(v.z);
    __nv_bfloat16 h3 = __float2bfloat16(v.w);
    __nv_bfloat16 l0 = __float2bfloat16(v.x - __bfloat162float(h0));
    __nv_bfloat16 l1 = __float2bfloat16(v.y - __bfloat162float(h1));
    __nv_bfloat16 l2 = __float2bfloat16(v.z - __bfloat162float(h2));
    __nv_bfloat16 l3 = __float2bfloat16(v.w - __bfloat162float(h3));
    __nv_bfloat162 hA; hA.x = h0; hA.y = h1;
    __nv_bfloat162 hB; hB.x = h2; hB.y = h3;
    __nv_bfloat162 lA; lA.x = l0; lA.y = l1;
    __nv_bfloat162 lB; lB.x = l2; lB.y = l3;
    uint2 hu; hu.x = *(uint32_t*)&hA; hu.y = *(uint32_t*)&hB;
    uint2 lu; lu.x = *(uint32_t*)&lA; lu.y = *(uint32_t*)&lB;
    *(uint2*)hiP = hu;
    *(uint2*)loP = lu;
}

struct Pref { float4 a[8]; float4 b[8]; };

__device__ __forceinline__ void do_loads(Pref& p, const float* __restrict__ Ap,
                                         const float* __restrict__ Bp, int k0, int tid) {
    #pragma unroll
    for (int j = 0; j < 8; j++) {
        int i = tid + j*GT;                // 0..2047
        int row = i >> 4, seg = i & 15;
        p.a[j] = *(const float4*)(Ap + (size_t)row*DD + k0 + seg*4);
        p.b[j] = *(const float4*)(Bp + (size_t)row*DD + k0 + seg*4);
    }
}

__device__ __forceinline__ void do_store(const Pref& p, char* smem, int stage, int tid) {
    char* base = smem + stage*STAGE_SZ;
    #pragma unroll
    for (int j = 0; j < 8; j++) {
        int i = tid + j*GT;
        int row = i >> 4, seg = i & 15;
        uint32_t dst = SWZ128((uint32_t)(row*128 + seg*8));
        cvt_f4(p.a[j], base + OFF_AHI + dst, base + OFF_ALO + dst);
        cvt_f4(p.b[j], base + OFF_BHI + dst, base + OFF_BLO + dst);
    }
}

__device__ __forceinline__ void mma_chunk(uint32_t sb, int lane, int warp_m, int warp_n,
                                          float acc[2][8][4]) {
    #pragma unroll
    for (int k16 = 0; k16 < 4; k16++) {
        uint32_t Ahi[2][4], Alo[2][4];
        #pragma unroll
        for (int mt = 0; mt < 2; mt++) {
            int row = warp_m + mt*16 + (lane & 7) + ((lane & 8) ? 8 : 0);
            int kb  = k16*32 + ((lane & 16) ? 16 : 0);
            uint32_t off = SWZ128((uint32_t)(row*128 + kb));
            LDSM_X4(Ahi[mt], sb + OFF_AHI + off);
            LDSM_X4(Alo[mt], sb + OFF_ALO + off);
        }
        #pragma unroll
        for (int nt = 0; nt < 8; nt++) {
            int l = lane & 15;
            int nrow = warp_n + nt*8 + (l & 7);
            int kb = k16*32 + ((l & 8) ? 16 : 0);
            uint32_t off = SWZ128((uint32_t)(nrow*128 + kb));
            uint32_t Bhi[2], Blo[2];
            LDSM_X2(Bhi, sb + OFF_BHI + off);
            LDSM_X2(Blo, sb + OFF_BLO + off);
            #pragma unroll
            for (int mt = 0; mt < 2; mt++) {
                mma16816(acc[mt][nt], Ahi[mt], Bhi);
                mma16816(acc[mt][nt], Alo[mt], Bhi);
                mma16816(acc[mt][nt], Ahi[mt], Blo);
            }
        }
    }
}

__global__ void __launch_bounds__(GT, 1) k_gemm_mma(const float* __restrict__ A,
                                                    const float* __restrict__ WK,
                                                    const float* __restrict__ WV) {
    extern __shared__ char smem[];
    const uint32_t sb0 = smem_u32(smem);
    const int tid = threadIdx.x;
    const int lane = tid & 31, wid = tid >> 5;
    const int warp_m = (wid & 3) * 32;
    const int warp_n = (wid >> 2) * 64;
    const int mBase = blockIdx.x * 128;
    const int nb = blockIdx.y;             // 0 -> k (W_K), 1 -> v (W_V)
    const float* Ap = A + (size_t)mBase * DD;
    const float* Bp = nb ? WV : WK;

    float acc[2][8][4];
    #pragma unroll
    for (int mt = 0; mt < 2; mt++)
        #pragma unroll
        for (int nt = 0; nt < 8; nt++)
            #pragma unroll
            for (int r = 0; r < 4; r++) acc[mt][nt][r] = 0.f;

    Pref p;
    do_loads(p, Ap, Bp, 0, tid);
    do_store(p, smem, 0, tid);
    __syncthreads();

    for (int c = 0; c < NCHUNK; c++) {
        if (c + 1 < NCHUNK) do_loads(p, Ap, Bp, (c + 1) * 64, tid);
        mma_chunk(sb0 + (c & 1) * STAGE_SZ, lane, warp_m, warp_n, acc);
        if (c + 1 < NCHUNK) do_store(p, smem, (c + 1) & 1, tid);
        __syncthreads();
    }

    // epilogue: direct stores to g_kv
    const int gr = lane >> 2, ci = lane & 3;
    #pragma unroll
    for (int mt = 0; mt < 2; mt++) {
        #pragma unroll
        for (int nt = 0; nt < 8; nt++) {
            int col = nb*128 + warp_n + nt*8 + 2*ci;
            int row = mBase + warp_m + mt*16 + gr;
            float2 v0; v0.x = acc[mt][nt][0]; v0.y = acc[mt][nt][1];
            float2 v1; v1.x = acc[mt][nt][2]; v1.y = acc[mt][nt][3];
            *(float2*)(g_kv + (size_t)row*256 + col) = v0;
            *(float2*)(g_kv + (size_t)(row + 8)*256 + col) = v1;
        }
    }
}

// -------- K5: per-(b,n) score + screening factor (one warp each) --------
__global__ void k_score(const float* __restrict__ zq, const float* __restrict__ zk,
                        const float* __restrict__ Wd, const float* __restrict__ logsig) {
    int gw = (blockIdx.x * blockDim.x + threadIdx.x) >> 5;
    if (gw >= BB*NN) return;
    int lane = threadIdx.x & 31;
    int b = gw >> 11, n = gw & (NN-1);

    float zq0 = zq[b*DLL + lane], zq1 = zq[b*DLL + 32 + lane];
    const float* zkp = zk + (size_t)(b*NN + n)*DLL;
    float d0 = zq0 - zkp[lane];
    float d1 = zq1 - zkp[32 + lane];

    float dist = d0*d0 + d1*d1;
    #pragma unroll
    for (int o = 16; o; o >>= 1) dist += __shfl_xor_sync(0xffffffffu, dist, o);

    float coeff[DCC];
    #pragma unroll
    for (int r = 0; r < DCC; r++) {
        float p = d0*Wd[r*DLL + lane] + d1*Wd[r*DLL + 32 + lane];
        #pragma unroll
        for (int o = 16; o; o >>= 1) p += __shfl_xor_sync(0xffffffffu, p, o);
        coeff[r] = p;
    }

    float s = 0.f;
    const float* kvp = g_kv + (size_t)(b*NN + n)*256;
    #pragma unroll
    for (int jj = 0; jj < 4; jj++) {
        int j = jj*32 + lane;
        float qe = g_q[b*DKK + j];
        #pragma unroll
        for (int r = 0; r < DCC; r++) qe += coeff[r]*g_qB[(b*DCC + r)*DKK + j];
        s += qe * kvp[j];
    }
    #pragma unroll
    for (int o = 16; o; o >>= 1) s += __shfl_xor_sync(0xffffffffu, s, o);

    if (lane == 0) {
        g_score[b*NN + n] = s;
        float lam = g_lam[b];
        float sig = expf(logsig[0]);
        g_screen[b*NN + n] = expf(-sig * 0.5f * lam * lam * dist);
    }
}

// -------- K6: per-b softmax stats (max, sum-exp) --------
__global__ void k_smax() {
    int b = blockIdx.x, t = threadIdx.x;   // 256 threads
    __shared__ float red[256];
    float m = -1e30f;
    for (int i = t; i < NN; i += 256) m = fmaxf(m, g_score[b*NN + i]);
    red[t] = m; __syncthreads();
    for (int o = 128; o; o >>= 1) { if (t < o) red[t] = fmaxf(red[t], red[t+o]); __syncthreads(); }
    m = red[0]; __syncthreads();
    float z = 0.f;
    for (int i = t; i < NN; i += 256) z += expf(g_score[b*NN + i] - m);
    red[t] = z; __syncthreads();
    for (int o = 128; o; o >>= 1) { if (t < o) red[t] += red[t+o]; __syncthreads(); }
    if (t == 0) { g_m[b] = m; g_Z[b] = red[0]; }
}

// -------- K7: partial av[b,a] = sum_n w_n * v[b,n,a] over 128-n slices --------
__global__ void k_av() {
    int b = blockIdx.x, s0 = blockIdx.y * 128;
    int t = threadIdx.x;                   // 128 threads (a index)
    __shared__ float w[128];
    int n = s0 + t;
    w[t] = expf(g_score[b*NN + n] - g_m[b]) / g_Z[b] * g_screen[b*NN + n];
    __syncthreads();
    float acc = 0.f;
    const float* vbase = g_kv + (size_t)(b*NN + s0)*256 + 128 + t;
    #pragma unroll 4
    for (int nn = 0; nn < 128; nn++) acc += w[nn] * vbase[(size_t)nn*256];
    g_avp[(b*16 + blockIdx.y)*DKK + t] = acc;
}

// -------- K7b: reduce partials --------
__global__ void k_avred() {
    int idx = threadIdx.x;                 // 512 threads
    int b = idx >> 7, a = idx & 127;
    float s = 0.f;
    #pragma unroll
    for (int p = 0; p < 16; p++) s += g_avp[(b*16 + p)*DKK + a];
    g_av[idx] = s;
}

// -------- K8: out[b,d] = sum_a av[b,a]*W_O[d,a] --------
__global__ void k_out(const float* __restrict__ WO, float* __restrict__ out) {
    int t = threadIdx.x;                   // 256 threads
    int idx = blockIdx.x * 256 + t;
    int b = idx >> 10, d = idx & 1023;
    __shared__ float av[DKK];
    if (t < DKK) av[t] = g_av[b*DKK + t];
    __syncthreads();
    float s = 0.f;
    const float4* wo = (const float4*)(WO + (size_t)d*DKK);
    #pragma unroll 8
    for (int a4 = 0; a4 < 32; a4++) {
        float4 wv = wo[a4];
        s += av[a4*4+0]*wv.x + av[a4*4+1]*wv.y + av[a4*4+2]*wv.z + av[a4*4+3]*wv.w;
    }
    out[idx] = s;
}

extern "C" void kernel_launch(void* const* d_in, const int* in_sizes, int n_in,
                              void* d_out, int out_size) {
    const float* x_query   = (const float*)d_in[0];
    const float* z_query   = (const float*)d_in[1];
    const float* x_keys    = (const float*)d_in[2];
    const float* z_keys    = (const float*)d_in[3];
    const float* W_Q       = (const float*)d_in[4];
    const float* W_Qz      = (const float*)d_in[5];
    const float* W_Qg      = (const float*)d_in[6];
    const float* W_K       = (const float*)d_in[7];
    const float* W_V       = (const float*)d_in[8];
    const float* W_O       = (const float*)d_in[9];
    const float* W_delta   = (const float*)d_in[10];
    const float* basis_b   = (const float*)d_in[11];
    const float* basis_e   = (const float*)d_in[12];
    const float* basis_o   = (const float*)d_in[13];
    const float* log_sigma = (const float*)d_in[14];
    float* out = (float*)d_out;

    cudaFuncSetAttribute(k_gemm_mma, cudaFuncAttributeMaxDynamicSharedMemorySize, GEMM_SMEM);

    k_basis<<<(DCC*DKK*DKK + 255)/256, 256>>>(basis_b, basis_e, basis_o);
    k_query<<<dim3(DKK, BB), 128>>>(x_query, z_query, W_Q, W_Qz, W_Qg);
    k_qB<<<dim3(DCC, BB), 128>>>();
    k_gemm_mma<<<dim3(64, 2), GT, GEMM_SMEM>>>(x_keys, W_K, W_V);
    k_score<<<(BB*NN*32)/256, 256>>>(z_query, z_keys, W_delta, log_sigma);
    k_smax<<<BB, 256>>>();
    k_av<<<dim3(BB, 16), 128>>>();
    k_avred<<<1, 512>>>();
    k_out<<<16, 256>>>(W_O, out);
}